// round 1
// baseline (speedup 1.0000x reference)
#include <cuda_runtime.h>
#include <math.h>

#define NB 32
#define NS 8192
#define ND 256
#define NCHUNK 32          // blocks per batch in main pass
#define POS_PER_BLOCK 256  // 8 warps * 32 positions
#define POS_PER_WARP 32

// ---------------- scratch (no allocation allowed) ----------------
__device__ float g_V[NB * ND];             // v[b] = Wa_w^T ht[b]
__device__ float g_c0[NB];                 // ht[b] . Wa_b
__device__ float g_PM[NB * NCHUNK];        // per-block partial max
__device__ float g_PL[NB * NCHUNK];        // per-block partial sum
__device__ float g_PA[NB * NCHUNK * ND];   // per-block partial weighted row-sum
__device__ float g_M[NB];                  // global max per batch
__device__ float g_Rinv[NB];               // 1 / global sum per batch

// ---------------- K1: precompute v[b], c0[b] ----------------
__global__ void k_pre(const float* __restrict__ ht,
                      const float* __restrict__ Wa_w,
                      const float* __restrict__ Wa_b) {
    int b = blockIdx.x, t = threadIdx.x;
    __shared__ float sh[ND];
    __shared__ float red[ND];
    sh[t] = ht[b * ND + t];
    __syncthreads();
    float acc = 0.f;
    #pragma unroll 8
    for (int d = 0; d < ND; d++)
        acc = fmaf(sh[d], Wa_w[d * ND + t], acc);  // coalesced across t
    g_V[b * ND + t] = acc;

    red[t] = sh[t] * Wa_b[t];
    __syncthreads();
    for (int s = 128; s > 0; s >>= 1) {
        if (t < s) red[t] += red[t + s];
        __syncthreads();
    }
    if (t == 0) g_c0[b] = red[0];
}

// ---------------- K2: fused energy + online softmax + weighted row-sum ----
__global__ void __launch_bounds__(256)
k_main(const float* __restrict__ hs, const int* __restrict__ slen,
       float* __restrict__ alpha /* energy staging = d_out alpha region */) {
    int chunk = blockIdx.x, b = blockIdx.y;
    int tid = threadIdx.x, w = tid >> 5, lane = tid & 31;
    int len = slen[b];
    float c0 = g_c0[b];

    const float4* v4 = (const float4*)(g_V + b * ND);
    float4 va = v4[lane], vb = v4[lane + 32];

    int s0 = chunk * POS_PER_BLOCK + w * POS_PER_WARP;
    const float4* row = (const float4*)(hs + ((size_t)b * NS + s0) * ND);

    float M = -1e30f, Lsum = 0.f;
    float4 Aa = make_float4(0.f, 0.f, 0.f, 0.f);
    float4 Ab = make_float4(0.f, 0.f, 0.f, 0.f);

    // software-pipelined row load: 64 float4 per row, 2 per lane
    float4 ra = row[lane];
    float4 rb = row[lane + 32];
    #pragma unroll 4
    for (int i = 0; i < POS_PER_WARP; i++) {
        float4 na = ra, nb = rb;
        if (i + 1 < POS_PER_WARP) {
            na = row[(i + 1) * 64 + lane];
            nb = row[(i + 1) * 64 + lane + 32];
        }
        float p = ra.x * va.x + ra.y * va.y + ra.z * va.z + ra.w * va.w
                + rb.x * vb.x + rb.y * vb.y + rb.z * vb.z + rb.w * vb.w;
        #pragma unroll
        for (int o = 16; o > 0; o >>= 1)
            p += __shfl_xor_sync(0xffffffffu, p, o);
        float e = p + c0;
        e = (e > 0.f) ? e : 0.2f * e;                 // leaky relu
        int s = s0 + i;
        if (s >= len) e = -10000.f;                   // length mask
        if (lane == 0) alpha[(size_t)b * NS + s] = e; // stage raw energy

        float Mn = fmaxf(M, e);
        float scale = __expf(M - Mn);
        float pe = __expf(e - Mn);
        Lsum = Lsum * scale + pe;
        Aa.x = Aa.x * scale + pe * ra.x;
        Aa.y = Aa.y * scale + pe * ra.y;
        Aa.z = Aa.z * scale + pe * ra.z;
        Aa.w = Aa.w * scale + pe * ra.w;
        Ab.x = Ab.x * scale + pe * rb.x;
        Ab.y = Ab.y * scale + pe * rb.y;
        Ab.z = Ab.z * scale + pe * rb.z;
        Ab.w = Ab.w * scale + pe * rb.w;
        M = Mn;
        ra = na; rb = nb;
    }

    // combine 8 warps within the block
    __shared__ float sM[8], sL[8];
    __shared__ float sA[8][ND];
    float* arow = sA[w];
    arow[lane * 4 + 0] = Aa.x; arow[lane * 4 + 1] = Aa.y;
    arow[lane * 4 + 2] = Aa.z; arow[lane * 4 + 3] = Aa.w;
    arow[128 + lane * 4 + 0] = Ab.x; arow[128 + lane * 4 + 1] = Ab.y;
    arow[128 + lane * 4 + 2] = Ab.z; arow[128 + lane * 4 + 3] = Ab.w;
    if (lane == 0) { sM[w] = M; sL[w] = Lsum; }
    __syncthreads();

    float Mb = sM[0];
    #pragma unroll
    for (int j = 1; j < 8; j++) Mb = fmaxf(Mb, sM[j]);
    float acc = 0.f, lb = 0.f;
    #pragma unroll
    for (int j = 0; j < 8; j++) {
        float sc = __expf(sM[j] - Mb);
        acc = fmaf(sc, sA[j][tid], acc);
        lb = fmaf(sc, sL[j], lb);
    }
    int pid = b * NCHUNK + chunk;
    g_PA[pid * ND + tid] = acc;
    if (tid == 0) { g_PM[pid] = Mb; g_PL[pid] = lb; }
}

// ---------------- K3: combine partials; context = Wc_w @ m + Wc_b --------
__global__ void __launch_bounds__(256)
k_combine(const float* __restrict__ Wc_w, const float* __restrict__ Wc_b,
          float* __restrict__ out_ctx) {
    int b = blockIdx.x, t = threadIdx.x, w = t >> 5, lane = t & 31;
    __shared__ float sM[NCHUNK], sL[NCHUNK];
    __shared__ __align__(16) float sm[ND];
    if (t < NCHUNK) {
        sM[t] = g_PM[b * NCHUNK + t];
        sL[t] = g_PL[b * NCHUNK + t];
    }
    __syncthreads();
    float Mg = sM[0];
    #pragma unroll
    for (int j = 1; j < NCHUNK; j++) Mg = fmaxf(Mg, sM[j]);
    float Lg = 0.f;
    #pragma unroll
    for (int j = 0; j < NCHUNK; j++) Lg = fmaf(sL[j], __expf(sM[j] - Mg), Lg);
    float m = 0.f;
    for (int j = 0; j < NCHUNK; j++)
        m = fmaf(__expf(sM[j] - Mg), g_PA[(b * NCHUNK + j) * ND + t], m);
    m /= Lg;
    sm[t] = m;
    if (t == 0) { g_M[b] = Mg; g_Rinv[b] = 1.f / Lg; }
    __syncthreads();

    const float4* m4 = (const float4*)sm;
    float4 ma = m4[lane], mb = m4[lane + 32];
    for (int d = w; d < ND; d += 8) {   // warp per output row, coalesced weight loads
        const float4* wr = (const float4*)(Wc_w + d * ND);
        float4 wa = wr[lane], wb = wr[lane + 32];
        float p = wa.x * ma.x + wa.y * ma.y + wa.z * ma.z + wa.w * ma.w
                + wb.x * mb.x + wb.y * mb.y + wb.z * mb.z + wb.w * mb.w;
        #pragma unroll
        for (int o = 16; o > 0; o >>= 1)
            p += __shfl_xor_sync(0xffffffffu, p, o);
        if (lane == 0) out_ctx[b * ND + d] = p + Wc_b[d];
    }
}

// ---------------- K4: normalize alpha in place ----------------
__global__ void k_norm(float* __restrict__ alpha) {
    int i = blockIdx.x * blockDim.x + threadIdx.x;   // over NB*NS
    int b = i >> 13;                                  // NS = 8192
    float e = alpha[i];
    alpha[i] = __expf(e - g_M[b]) * g_Rinv[b];
}

// ---------------- launch ----------------
extern "C" void kernel_launch(void* const* d_in, const int* in_sizes, int n_in,
                              void* d_out, int out_size) {
    const float* hs   = (const float*)d_in[0];  // [B,S,256]
    const float* ht   = (const float*)d_in[1];  // [B,256]
    const int*   slen = (const int*)  d_in[2];  // [B]
    const float* Wa_w = (const float*)d_in[3];  // [256,256]
    const float* Wa_b = (const float*)d_in[4];  // [256]
    const float* Wc_w = (const float*)d_in[5];  // [256,256]
    const float* Wc_b = (const float*)d_in[6];  // [256]

    float* alpha = (float*)d_out;               // [B,S]
    float* ctx   = (float*)d_out + (size_t)NB * NS;  // [B,256]

    k_pre<<<NB, 256>>>(ht, Wa_w, Wa_b);
    dim3 grid2(NCHUNK, NB);
    k_main<<<grid2, 256>>>(hs, slen, alpha);
    k_combine<<<NB, 256>>>(Wc_w, Wc_b, ctx);
    k_norm<<<(NB * NS) / 256, 256>>>(alpha);
}

// round 2
// speedup vs baseline: 1.3892x; 1.3892x over previous
#include <cuda_runtime.h>
#include <math.h>

#define NB 32
#define NS 8192
#define ND 256
#define NCHUNK 32          // blocks per batch in main pass
#define POS_PER_BLOCK 256  // 8 warps * 32 positions
#define POS_PER_WARP 32

// ---------------- scratch (no allocation allowed) ----------------
__device__ float g_V[NB * ND];             // v[b] = Wa_w^T ht[b]
__device__ float g_c0[NB];                 // ht[b] . Wa_b
__device__ float g_PM[NB * NCHUNK];        // per-block partial max
__device__ float g_PL[NB * NCHUNK];        // per-block partial sum
__device__ float g_PA[NB * NCHUNK * ND];   // per-block partial weighted row-sum
__device__ float g_M[NB];                  // global max per batch
__device__ float g_Rinv[NB];               // 1 / global sum per batch

// ---------------- K1: precompute v[b], c0[b] ----------------
__global__ void k_pre(const float* __restrict__ ht,
                      const float* __restrict__ Wa_w,
                      const float* __restrict__ Wa_b) {
    int b = blockIdx.x, t = threadIdx.x;
    __shared__ float sh[ND];
    __shared__ float red[ND];
    sh[t] = ht[b * ND + t];
    __syncthreads();
    float acc = 0.f;
    #pragma unroll 8
    for (int d = 0; d < ND; d++)
        acc = fmaf(sh[d], Wa_w[d * ND + t], acc);  // coalesced across t
    g_V[b * ND + t] = acc;

    red[t] = sh[t] * Wa_b[t];
    __syncthreads();
    for (int s = 128; s > 0; s >>= 1) {
        if (t < s) red[t] += red[t + s];
        __syncthreads();
    }
    if (t == 0) g_c0[b] = red[0];
}

// ---------------- K2: fused energy + online softmax + weighted row-sum ----
// 2 rows per warp-iteration, pair-prefetched (4 LDG.128 in flight / warp).
// Only rows < len_eff are processed (masked tail contributes exactly 0).
__global__ void __launch_bounds__(256)
k_main(const float* __restrict__ hs, const int* __restrict__ slen,
       float* __restrict__ alpha /* energy staging = d_out alpha region */) {
    int chunk = blockIdx.x, b = blockIdx.y;
    int tid = threadIdx.x, w = tid >> 5, lane = tid & 31;
    int len = slen[b];
    int len_eff = (len == 0) ? NS : len;    // len==0: all masked -> uniform softmax, full work

    if (chunk * POS_PER_BLOCK >= len_eff) return;   // whole block past valid region

    float c0 = g_c0[b];
    const float4* v4 = (const float4*)(g_V + b * ND);
    float4 va = v4[lane], vb = v4[lane + 32];

    int s0 = chunk * POS_PER_BLOCK + w * POS_PER_WARP;
    bool active = (s0 < len_eff);

    float M = -1e30f, Lsum = 0.f;
    float4 Aa = make_float4(0.f, 0.f, 0.f, 0.f);
    float4 Ab = make_float4(0.f, 0.f, 0.f, 0.f);

    if (active) {
        const float4* row = (const float4*)(hs + ((size_t)b * NS + s0) * ND);
        // prefetch first pair of rows (4 x float4 per lane in flight)
        float4 r1a = row[lane],       r1b = row[lane + 32];
        float4 r2a = row[64 + lane],  r2b = row[64 + lane + 32];

        #pragma unroll 2
        for (int i = 0; i < POS_PER_WARP / 2; i++) {
            float4 n1a = r1a, n1b = r1b, n2a = r2a, n2b = r2b;
            if (i + 1 < POS_PER_WARP / 2) {
                const float4* nx = row + (2 * i + 2) * 64;
                n1a = nx[lane];       n1b = nx[lane + 32];
                n2a = nx[64 + lane];  n2b = nx[64 + lane + 32];
            }
            float p1 = r1a.x * va.x + r1a.y * va.y + r1a.z * va.z + r1a.w * va.w
                     + r1b.x * vb.x + r1b.y * vb.y + r1b.z * vb.z + r1b.w * vb.w;
            float p2 = r2a.x * va.x + r2a.y * va.y + r2a.z * va.z + r2a.w * va.w
                     + r2b.x * vb.x + r2b.y * vb.y + r2b.z * vb.z + r2b.w * vb.w;
            #pragma unroll
            for (int o = 16; o > 0; o >>= 1) {       // two independent chains, ILP 2
                p1 += __shfl_xor_sync(0xffffffffu, p1, o);
                p2 += __shfl_xor_sync(0xffffffffu, p2, o);
            }
            int s1 = s0 + 2 * i, s2 = s1 + 1;
            float e1 = p1 + c0, e2 = p2 + c0;
            e1 = (e1 > 0.f) ? e1 : 0.2f * e1;        // leaky relu
            e2 = (e2 > 0.f) ? e2 : 0.2f * e2;
            if (s1 >= len) e1 = -10000.f;            // length mask (real len)
            if (s2 >= len) e2 = -10000.f;
            if (lane == 0) {
                float2 st = make_float2(e1, e2);
                *(float2*)(alpha + (size_t)b * NS + s1) = st;  // stage raw energies
            }

            float Mn = fmaxf(M, fmaxf(e1, e2));
            float scale = __expf(M - Mn);
            float pe1 = __expf(e1 - Mn);
            float pe2 = __expf(e2 - Mn);
            Lsum = Lsum * scale + pe1 + pe2;
            Aa.x = fmaf(pe2, r2a.x, fmaf(pe1, r1a.x, Aa.x * scale));
            Aa.y = fmaf(pe2, r2a.y, fmaf(pe1, r1a.y, Aa.y * scale));
            Aa.z = fmaf(pe2, r2a.z, fmaf(pe1, r1a.z, Aa.z * scale));
            Aa.w = fmaf(pe2, r2a.w, fmaf(pe1, r1a.w, Aa.w * scale));
            Ab.x = fmaf(pe2, r2b.x, fmaf(pe1, r1b.x, Ab.x * scale));
            Ab.y = fmaf(pe2, r2b.y, fmaf(pe1, r1b.y, Ab.y * scale));
            Ab.z = fmaf(pe2, r2b.z, fmaf(pe1, r1b.z, Ab.z * scale));
            Ab.w = fmaf(pe2, r2b.w, fmaf(pe1, r1b.w, Ab.w * scale));
            M = Mn;
            r1a = n1a; r1b = n1b; r2a = n2a; r2b = n2b;
        }
    }

    // combine 8 warps within the block
    __shared__ float sM[8], sL[8];
    __shared__ float sA[8][ND];
    float* arow = sA[w];
    arow[lane * 4 + 0] = Aa.x; arow[lane * 4 + 1] = Aa.y;
    arow[lane * 4 + 2] = Aa.z; arow[lane * 4 + 3] = Aa.w;
    arow[128 + lane * 4 + 0] = Ab.x; arow[128 + lane * 4 + 1] = Ab.y;
    arow[128 + lane * 4 + 2] = Ab.z; arow[128 + lane * 4 + 3] = Ab.w;
    if (lane == 0) { sM[w] = M; sL[w] = Lsum; }
    __syncthreads();

    float Mb = sM[0];
    #pragma unroll
    for (int j = 1; j < 8; j++) Mb = fmaxf(Mb, sM[j]);
    float acc = 0.f, lb = 0.f;
    #pragma unroll
    for (int j = 0; j < 8; j++) {
        float sc = __expf(sM[j] - Mb);   // sM=-1e30 (inactive warp) -> sc=0
        acc = fmaf(sc, sA[j][tid], acc);
        lb = fmaf(sc, sL[j], lb);
    }
    int pid = b * NCHUNK + chunk;
    g_PA[pid * ND + tid] = acc;
    if (tid == 0) { g_PM[pid] = Mb; g_PL[pid] = lb; }
}

// ---------------- K3: combine partials; context = Wc_w @ m + Wc_b --------
__global__ void __launch_bounds__(256)
k_combine(const float* __restrict__ Wc_w, const float* __restrict__ Wc_b,
          const int* __restrict__ slen, float* __restrict__ out_ctx) {
    int b = blockIdx.x, t = threadIdx.x, w = t >> 5, lane = t & 31;
    int len = slen[b];
    int len_eff = (len == 0) ? NS : len;
    int nval = (len_eff + POS_PER_BLOCK - 1) / POS_PER_BLOCK;   // valid chunks only

    __shared__ float sM[NCHUNK], sL[NCHUNK];
    __shared__ __align__(16) float sm[ND];
    if (t < NCHUNK && t < nval) {
        sM[t] = g_PM[b * NCHUNK + t];
        sL[t] = g_PL[b * NCHUNK + t];
    }
    __syncthreads();
    float Mg = sM[0];
    for (int j = 1; j < nval; j++) Mg = fmaxf(Mg, sM[j]);
    float Lg = 0.f;
    for (int j = 0; j < nval; j++) Lg = fmaf(sL[j], __expf(sM[j] - Mg), Lg);
    float m = 0.f;
    for (int j = 0; j < nval; j++)
        m = fmaf(__expf(sM[j] - Mg), g_PA[(b * NCHUNK + j) * ND + t], m);
    m /= Lg;
    sm[t] = m;
    if (t == 0) { g_M[b] = Mg; g_Rinv[b] = 1.f / Lg; }
    __syncthreads();

    const float4* m4 = (const float4*)sm;
    float4 ma = m4[lane], mb = m4[lane + 32];
    for (int d = w; d < ND; d += 8) {   // warp per output row, coalesced weight loads
        const float4* wr = (const float4*)(Wc_w + d * ND);
        float4 wa = wr[lane], wb = wr[lane + 32];
        float p = wa.x * ma.x + wa.y * ma.y + wa.z * ma.z + wa.w * ma.w
                + wb.x * mb.x + wb.y * mb.y + wb.z * mb.z + wb.w * mb.w;
        #pragma unroll
        for (int o = 16; o > 0; o >>= 1)
            p += __shfl_xor_sync(0xffffffffu, p, o);
        if (lane == 0) out_ctx[b * ND + d] = p + Wc_b[d];
    }
}

// ---------------- K4: normalize alpha in place (float4/thread) ----------
__global__ void k_norm(float* __restrict__ alpha, const int* __restrict__ slen) {
    int i4 = blockIdx.x * blockDim.x + threadIdx.x;   // over NB*NS/4 = 65536
    int b = i4 >> 11;                                 // 2048 float4 per batch
    int len = slen[b];
    float M = g_M[b], R = g_Rinv[b];
    float4 e = ((const float4*)alpha)[i4];
    int pos = (i4 & 2047) * 4;
    float4 o;
    o.x = (len > 0 && pos + 0 >= len) ? 0.f : __expf(e.x - M) * R;
    o.y = (len > 0 && pos + 1 >= len) ? 0.f : __expf(e.y - M) * R;
    o.z = (len > 0 && pos + 2 >= len) ? 0.f : __expf(e.z - M) * R;
    o.w = (len > 0 && pos + 3 >= len) ? 0.f : __expf(e.w - M) * R;
    ((float4*)alpha)[i4] = o;
}

// ---------------- launch ----------------
extern "C" void kernel_launch(void* const* d_in, const int* in_sizes, int n_in,
                              void* d_out, int out_size) {
    const float* hs   = (const float*)d_in[0];  // [B,S,256]
    const float* ht   = (const float*)d_in[1];  // [B,256]
    const int*   slen = (const int*)  d_in[2];  // [B]
    const float* Wa_w = (const float*)d_in[3];  // [256,256]
    const float* Wa_b = (const float*)d_in[4];  // [256]
    const float* Wc_w = (const float*)d_in[5];  // [256,256]
    const float* Wc_b = (const float*)d_in[6];  // [256]

    float* alpha = (float*)d_out;               // [B,S]
    float* ctx   = (float*)d_out + (size_t)NB * NS;  // [B,256]

    k_pre<<<NB, 256>>>(ht, Wa_w, Wa_b);
    dim3 grid2(NCHUNK, NB);
    k_main<<<grid2, 256>>>(hs, slen, alpha);
    k_combine<<<NB, 256>>>(Wc_w, Wc_b, slen, ctx);
    k_norm<<<(NB * NS) / (256 * 4), 256>>>(alpha, slen);
}

// round 3
// speedup vs baseline: 1.6179x; 1.1646x over previous
#include <cuda_runtime.h>
#include <math.h>

#define NB 32
#define NS 8192
#define ND 256
#define NCHUNK 64          // blocks per batch in main pass
#define POS_PER_BLOCK 128  // 8 warps * 16 positions
#define POS_PER_WARP 16

// ---------------- scratch (no allocation allowed) ----------------
__device__ float g_V[NB * ND];             // v[b] = Wa_w^T ht[b]
__device__ float g_c0[NB];                 // ht[b] . Wa_b
__device__ float g_PM[NB * NCHUNK];        // per-block partial max
__device__ float g_PL[NB * NCHUNK];        // per-block partial sum
__device__ float g_PA[NB * NCHUNK * ND];   // per-block partial weighted row-sum

// ---------------- K1: precompute v[b], c0[b] ----------------
__global__ void k_pre(const float* __restrict__ ht,
                      const float* __restrict__ Wa_w,
                      const float* __restrict__ Wa_b) {
    int b = blockIdx.x, t = threadIdx.x;
    __shared__ float sh[ND];
    __shared__ float red[ND];
    sh[t] = ht[b * ND + t];
    __syncthreads();
    float acc = 0.f;
    #pragma unroll 8
    for (int d = 0; d < ND; d++)
        acc = fmaf(sh[d], Wa_w[d * ND + t], acc);  // coalesced across t
    g_V[b * ND + t] = acc;

    red[t] = sh[t] * Wa_b[t];
    __syncthreads();
    for (int s = 128; s > 0; s >>= 1) {
        if (t < s) red[t] += red[t + s];
        __syncthreads();
    }
    if (t == 0) g_c0[b] = red[0];
}

// ---------------- K2: fused energy + online softmax + weighted row-sum ----
// 4 rows per warp-iteration, 8 LDG.128/lane issued per iteration (MLP 8),
// 4-way ILP shuffle reduce. Only chunks/warps below len_eff do work.
__global__ void __launch_bounds__(256)
k_main(const float* __restrict__ hs, const int* __restrict__ slen,
       float* __restrict__ alpha /* energy staging = d_out alpha region */) {
    int chunk = blockIdx.x, b = blockIdx.y;
    int tid = threadIdx.x, w = tid >> 5, lane = tid & 31;
    int len = slen[b];
    int len_eff = (len == 0) ? NS : len;    // len==0: uniform softmax, full work

    if (chunk * POS_PER_BLOCK >= len_eff) return;

    float c0 = g_c0[b];
    const float4* v4 = (const float4*)(g_V + b * ND);
    float4 va = v4[lane], vb = v4[lane + 32];

    int s0 = chunk * POS_PER_BLOCK + w * POS_PER_WARP;
    bool active = (s0 < len_eff);

    float M = -1e30f, Lsum = 0.f;
    float4 Aa = make_float4(0.f, 0.f, 0.f, 0.f);
    float4 Ab = make_float4(0.f, 0.f, 0.f, 0.f);

    if (active) {
        const float4* row = (const float4*)(hs + ((size_t)b * NS + s0) * ND);
        #pragma unroll 1
        for (int i = 0; i < POS_PER_WARP / 4; i++) {
            const float4* r = row + i * 4 * 64;      // row pitch = 64 float4
            // 8 independent LDG.128 per lane
            float4 r0a = r[lane],            r0b = r[lane + 32];
            float4 r1a = r[64 + lane],       r1b = r[64 + lane + 32];
            float4 r2a = r[128 + lane],      r2b = r[128 + lane + 32];
            float4 r3a = r[192 + lane],      r3b = r[192 + lane + 32];

            float p0 = r0a.x*va.x + r0a.y*va.y + r0a.z*va.z + r0a.w*va.w
                     + r0b.x*vb.x + r0b.y*vb.y + r0b.z*vb.z + r0b.w*vb.w;
            float p1 = r1a.x*va.x + r1a.y*va.y + r1a.z*va.z + r1a.w*va.w
                     + r1b.x*vb.x + r1b.y*vb.y + r1b.z*vb.z + r1b.w*vb.w;
            float p2 = r2a.x*va.x + r2a.y*va.y + r2a.z*va.z + r2a.w*va.w
                     + r2b.x*vb.x + r2b.y*vb.y + r2b.z*vb.z + r2b.w*vb.w;
            float p3 = r3a.x*va.x + r3a.y*va.y + r3a.z*va.z + r3a.w*va.w
                     + r3b.x*vb.x + r3b.y*vb.y + r3b.z*vb.z + r3b.w*vb.w;
            #pragma unroll
            for (int o = 16; o > 0; o >>= 1) {       // 4 independent chains
                p0 += __shfl_xor_sync(0xffffffffu, p0, o);
                p1 += __shfl_xor_sync(0xffffffffu, p1, o);
                p2 += __shfl_xor_sync(0xffffffffu, p2, o);
                p3 += __shfl_xor_sync(0xffffffffu, p3, o);
            }
            int s = s0 + 4 * i;
            float e0 = p0 + c0, e1 = p1 + c0, e2 = p2 + c0, e3 = p3 + c0;
            e0 = (e0 > 0.f) ? e0 : 0.2f * e0;        // leaky relu
            e1 = (e1 > 0.f) ? e1 : 0.2f * e1;
            e2 = (e2 > 0.f) ? e2 : 0.2f * e2;
            e3 = (e3 > 0.f) ? e3 : 0.2f * e3;
            if (s + 0 >= len) e0 = -10000.f;         // length mask (real len)
            if (s + 1 >= len) e1 = -10000.f;
            if (s + 2 >= len) e2 = -10000.f;
            if (s + 3 >= len) e3 = -10000.f;
            if (lane == 0)
                *(float4*)(alpha + (size_t)b * NS + s) = make_float4(e0, e1, e2, e3);

            float Mn = fmaxf(fmaxf(M, fmaxf(e0, e1)), fmaxf(e2, e3));
            float scale = __expf(M - Mn);
            float q0 = __expf(e0 - Mn), q1 = __expf(e1 - Mn);
            float q2 = __expf(e2 - Mn), q3 = __expf(e3 - Mn);
            Lsum = Lsum * scale + (q0 + q1) + (q2 + q3);
            Aa.x = fmaf(q3,r3a.x, fmaf(q2,r2a.x, fmaf(q1,r1a.x, fmaf(q0,r0a.x, Aa.x*scale))));
            Aa.y = fmaf(q3,r3a.y, fmaf(q2,r2a.y, fmaf(q1,r1a.y, fmaf(q0,r0a.y, Aa.y*scale))));
            Aa.z = fmaf(q3,r3a.z, fmaf(q2,r2a.z, fmaf(q1,r1a.z, fmaf(q0,r0a.z, Aa.z*scale))));
            Aa.w = fmaf(q3,r3a.w, fmaf(q2,r2a.w, fmaf(q1,r1a.w, fmaf(q0,r0a.w, Aa.w*scale))));
            Ab.x = fmaf(q3,r3b.x, fmaf(q2,r2b.x, fmaf(q1,r1b.x, fmaf(q0,r0b.x, Ab.x*scale))));
            Ab.y = fmaf(q3,r3b.y, fmaf(q2,r2b.y, fmaf(q1,r1b.y, fmaf(q0,r0b.y, Ab.y*scale))));
            Ab.z = fmaf(q3,r3b.z, fmaf(q2,r2b.z, fmaf(q1,r1b.z, fmaf(q0,r0b.z, Ab.z*scale))));
            Ab.w = fmaf(q3,r3b.w, fmaf(q2,r2b.w, fmaf(q1,r1b.w, fmaf(q0,r0b.w, Ab.w*scale))));
            M = Mn;
        }
    }

    // combine 8 warps within the block
    __shared__ float sM[8], sL[8];
    __shared__ float sA[8][ND];
    float* arow = sA[w];
    arow[lane * 4 + 0] = Aa.x; arow[lane * 4 + 1] = Aa.y;
    arow[lane * 4 + 2] = Aa.z; arow[lane * 4 + 3] = Aa.w;
    arow[128 + lane * 4 + 0] = Ab.x; arow[128 + lane * 4 + 1] = Ab.y;
    arow[128 + lane * 4 + 2] = Ab.z; arow[128 + lane * 4 + 3] = Ab.w;
    if (lane == 0) { sM[w] = M; sL[w] = Lsum; }
    __syncthreads();

    float Mb = sM[0];
    #pragma unroll
    for (int j = 1; j < 8; j++) Mb = fmaxf(Mb, sM[j]);
    float acc = 0.f, lb = 0.f;
    #pragma unroll
    for (int j = 0; j < 8; j++) {
        float sc = __expf(sM[j] - Mb);   // sM=-1e30 (inactive warp) -> 0
        acc = fmaf(sc, sA[j][tid], acc);
        lb = fmaf(sc, sL[j], lb);
    }
    int pid = b * NCHUNK + chunk;
    g_PA[pid * ND + tid] = acc;
    if (tid == 0) { g_PM[pid] = Mb; g_PL[pid] = lb; }
}

// ---------------- K3: combine + context GEMV + alpha normalize -----------
__global__ void __launch_bounds__(256)
k_fin(const float* __restrict__ Wc_w, const float* __restrict__ Wc_b,
      const int* __restrict__ slen, float* __restrict__ alpha,
      float* __restrict__ out_ctx) {
    int b = blockIdx.x, t = threadIdx.x, w = t >> 5, lane = t & 31;
    int len = slen[b];
    int len_eff = (len == 0) ? NS : len;
    int nval = (len_eff + POS_PER_BLOCK - 1) / POS_PER_BLOCK;   // valid chunks

    __shared__ float sM[NCHUNK], sL[NCHUNK];
    __shared__ __align__(16) float sm[ND];
    if (t < NCHUNK) {
        sM[t] = (t < nval) ? g_PM[b * NCHUNK + t] : -1e30f;
        sL[t] = (t < nval) ? g_PL[b * NCHUNK + t] : 0.f;
    }
    __syncthreads();
    float Mg = sM[0];
    #pragma unroll 8
    for (int j = 1; j < NCHUNK; j++) Mg = fmaxf(Mg, sM[j]);
    float Lg = 0.f;
    #pragma unroll 8
    for (int j = 0; j < NCHUNK; j++) Lg = fmaf(sL[j], __expf(sM[j] - Mg), Lg);
    float m = 0.f;
    #pragma unroll 4
    for (int j = 0; j < nval; j++)
        m = fmaf(__expf(sM[j] - Mg), g_PA[(b * NCHUNK + j) * ND + t], m);
    float Rinv = 1.f / Lg;
    m *= Rinv;
    sm[t] = m;
    __syncthreads();

    // context GEMV: warp per output row
    const float4* m4 = (const float4*)sm;
    float4 ma = m4[lane], mb = m4[lane + 32];
    #pragma unroll
    for (int d = w; d < ND; d += 8) {
        const float4* wr = (const float4*)(Wc_w + d * ND);
        float4 wa = wr[lane], wb = wr[lane + 32];
        float p = wa.x*ma.x + wa.y*ma.y + wa.z*ma.z + wa.w*ma.w
                + wb.x*mb.x + wb.y*mb.y + wb.z*mb.z + wb.w*mb.w;
        #pragma unroll
        for (int o = 16; o > 0; o >>= 1)
            p += __shfl_xor_sync(0xffffffffu, p, o);
        if (lane == 0) out_ctx[b * ND + d] = p + Wc_b[d];
    }

    // normalize this batch's alpha: 2048 float4, 8 per thread, loads 8-deep
    float4* a4 = (float4*)(alpha + (size_t)b * NS);
    float4 ev[8];
    #pragma unroll
    for (int k = 0; k < 8; k++) ev[k] = a4[k * 256 + t];
    #pragma unroll
    for (int k = 0; k < 8; k++) {
        int pos = (k * 256 + t) * 4;
        float4 o;
        if (len > 0 && pos >= len) {           // fully masked group
            o = make_float4(0.f, 0.f, 0.f, 0.f);
        } else {
            o.x = (len > 0 && pos + 0 >= len) ? 0.f : __expf(ev[k].x - Mg) * Rinv;
            o.y = (len > 0 && pos + 1 >= len) ? 0.f : __expf(ev[k].y - Mg) * Rinv;
            o.z = (len > 0 && pos + 2 >= len) ? 0.f : __expf(ev[k].z - Mg) * Rinv;
            o.w = (len > 0 && pos + 3 >= len) ? 0.f : __expf(ev[k].w - Mg) * Rinv;
        }
        a4[k * 256 + t] = o;
    }
}

// ---------------- launch ----------------
extern "C" void kernel_launch(void* const* d_in, const int* in_sizes, int n_in,
                              void* d_out, int out_size) {
    const float* hs   = (const float*)d_in[0];  // [B,S,256]
    const float* ht   = (const float*)d_in[1];  // [B,256]
    const int*   slen = (const int*)  d_in[2];  // [B]
    const float* Wa_w = (const float*)d_in[3];  // [256,256]
    const float* Wa_b = (const float*)d_in[4];  // [256]
    const float* Wc_w = (const float*)d_in[5];  // [256,256]
    const float* Wc_b = (const float*)d_in[6];  // [256]

    float* alpha = (float*)d_out;                    // [B,S]
    float* ctx   = (float*)d_out + (size_t)NB * NS;  // [B,256]

    k_pre<<<NB, 256>>>(ht, Wa_w, Wa_b);
    dim3 grid2(NCHUNK, NB);
    k_main<<<grid2, 256>>>(hs, slen, alpha);
    k_fin<<<NB, 256>>>(Wc_w, Wc_b, slen, alpha, ctx);
}

// round 4
// speedup vs baseline: 2.0343x; 1.2574x over previous
#include <cuda_runtime.h>
#include <math.h>

#define NB 32
#define NS 8192
#define ND 256
#define NCHUNK 64          // blocks per batch in main pass
#define POS_PER_BLOCK 128  // 8 warps * 16 positions
#define POS_PER_WARP 16
#define NPRE 4             // k_pre reduction split

// ---------------- scratch (no allocation allowed) ----------------
__device__ float g_Vp[NB * NPRE * ND];     // partial v[b] = Wa_w^T ht[b], split over d
__device__ float g_c0[NB];                 // ht[b] . Wa_b
__device__ float g_PM[NB * NCHUNK];        // per-block partial max
__device__ float g_PL[NB * NCHUNK];        // per-block partial sum
__device__ float g_PA[NB * NCHUNK * ND];   // per-block partial weighted row-sum

// ---------------- K1: partial v[b], c0[b] (4-way split over d) -----------
__global__ void __launch_bounds__(256)
k_pre(const float* __restrict__ ht,
      const float* __restrict__ Wa_w,
      const float* __restrict__ Wa_b) {
    int g = blockIdx.x, b = blockIdx.y, t = threadIdx.x;
    __shared__ float sh[64];
    if (t < 64) sh[t] = ht[b * ND + g * 64 + t];
    __syncthreads();
    const float* Wp = Wa_w + (size_t)(g * 64) * ND + t;
    float acc = 0.f;
    #pragma unroll 16
    for (int d = 0; d < 64; d++)
        acc = fmaf(sh[d], Wp[(size_t)d * ND], acc);   // coalesced across t, MLP via unroll
    g_Vp[(b * NPRE + g) * ND + t] = acc;

    if (g == 0) {   // c0 = ht . Wa_b
        __shared__ float red[ND];
        red[t] = ht[b * ND + t] * Wa_b[t];
        __syncthreads();
        for (int s = 128; s > 0; s >>= 1) {
            if (t < s) red[t] += red[t + s];
            __syncthreads();
        }
        if (t == 0) g_c0[b] = red[0];
    }
}

// ---------------- K2: fused energy + online softmax + weighted row-sum ----
// 4 rows per warp-iteration, 8 LDG.128/lane issued per iteration (MLP 8),
// 4-way ILP shuffle reduce. Only chunks/warps below len_eff do work.
__global__ void __launch_bounds__(256)
k_main(const float* __restrict__ hs, const int* __restrict__ slen,
       float* __restrict__ alpha /* energy staging = d_out alpha region */) {
    int chunk = blockIdx.x, b = blockIdx.y;
    int tid = threadIdx.x, w = tid >> 5, lane = tid & 31;
    int len = slen[b];
    int len_eff = (len == 0) ? NS : len;    // len==0: uniform softmax, full work

    if (chunk * POS_PER_BLOCK >= len_eff) return;

    float c0 = g_c0[b];

    // fold the 4 k_pre partials: v fragments for this lane
    const float4* vp = (const float4*)(g_Vp + (size_t)b * NPRE * ND);
    float4 va = vp[lane], vb = vp[lane + 32];
    #pragma unroll
    for (int g = 1; g < NPRE; g++) {
        float4 pa = vp[g * 64 + lane], pb = vp[g * 64 + lane + 32];
        va.x += pa.x; va.y += pa.y; va.z += pa.z; va.w += pa.w;
        vb.x += pb.x; vb.y += pb.y; vb.z += pb.z; vb.w += pb.w;
    }

    int s0 = chunk * POS_PER_BLOCK + w * POS_PER_WARP;
    bool active = (s0 < len_eff);

    float M = -1e30f, Lsum = 0.f;
    float4 Aa = make_float4(0.f, 0.f, 0.f, 0.f);
    float4 Ab = make_float4(0.f, 0.f, 0.f, 0.f);

    if (active) {
        const float4* row = (const float4*)(hs + ((size_t)b * NS + s0) * ND);
        #pragma unroll 1
        for (int i = 0; i < POS_PER_WARP / 4; i++) {
            const float4* r = row + i * 4 * 64;      // row pitch = 64 float4
            // 8 independent LDG.128 per lane
            float4 r0a = r[lane],            r0b = r[lane + 32];
            float4 r1a = r[64 + lane],       r1b = r[64 + lane + 32];
            float4 r2a = r[128 + lane],      r2b = r[128 + lane + 32];
            float4 r3a = r[192 + lane],      r3b = r[192 + lane + 32];

            float p0 = r0a.x*va.x + r0a.y*va.y + r0a.z*va.z + r0a.w*va.w
                     + r0b.x*vb.x + r0b.y*vb.y + r0b.z*vb.z + r0b.w*vb.w;
            float p1 = r1a.x*va.x + r1a.y*va.y + r1a.z*va.z + r1a.w*va.w
                     + r1b.x*vb.x + r1b.y*vb.y + r1b.z*vb.z + r1b.w*vb.w;
            float p2 = r2a.x*va.x + r2a.y*va.y + r2a.z*va.z + r2a.w*va.w
                     + r2b.x*vb.x + r2b.y*vb.y + r2b.z*vb.z + r2b.w*vb.w;
            float p3 = r3a.x*va.x + r3a.y*va.y + r3a.z*va.z + r3a.w*va.w
                     + r3b.x*vb.x + r3b.y*vb.y + r3b.z*vb.z + r3b.w*vb.w;
            #pragma unroll
            for (int o = 16; o > 0; o >>= 1) {       // 4 independent chains
                p0 += __shfl_xor_sync(0xffffffffu, p0, o);
                p1 += __shfl_xor_sync(0xffffffffu, p1, o);
                p2 += __shfl_xor_sync(0xffffffffu, p2, o);
                p3 += __shfl_xor_sync(0xffffffffu, p3, o);
            }
            int s = s0 + 4 * i;
            float e0 = p0 + c0, e1 = p1 + c0, e2 = p2 + c0, e3 = p3 + c0;
            e0 = (e0 > 0.f) ? e0 : 0.2f * e0;        // leaky relu
            e1 = (e1 > 0.f) ? e1 : 0.2f * e1;
            e2 = (e2 > 0.f) ? e2 : 0.2f * e2;
            e3 = (e3 > 0.f) ? e3 : 0.2f * e3;
            if (s + 0 >= len) e0 = -10000.f;         // length mask (real len)
            if (s + 1 >= len) e1 = -10000.f;
            if (s + 2 >= len) e2 = -10000.f;
            if (s + 3 >= len) e3 = -10000.f;
            if (lane == 0)
                *(float4*)(alpha + (size_t)b * NS + s) = make_float4(e0, e1, e2, e3);

            float Mn = fmaxf(fmaxf(M, fmaxf(e0, e1)), fmaxf(e2, e3));
            float scale = __expf(M - Mn);
            float q0 = __expf(e0 - Mn), q1 = __expf(e1 - Mn);
            float q2 = __expf(e2 - Mn), q3 = __expf(e3 - Mn);
            Lsum = Lsum * scale + (q0 + q1) + (q2 + q3);
            Aa.x = fmaf(q3,r3a.x, fmaf(q2,r2a.x, fmaf(q1,r1a.x, fmaf(q0,r0a.x, Aa.x*scale))));
            Aa.y = fmaf(q3,r3a.y, fmaf(q2,r2a.y, fmaf(q1,r1a.y, fmaf(q0,r0a.y, Aa.y*scale))));
            Aa.z = fmaf(q3,r3a.z, fmaf(q2,r2a.z, fmaf(q1,r1a.z, fmaf(q0,r0a.z, Aa.z*scale))));
            Aa.w = fmaf(q3,r3a.w, fmaf(q2,r2a.w, fmaf(q1,r1a.w, fmaf(q0,r0a.w, Aa.w*scale))));
            Ab.x = fmaf(q3,r3b.x, fmaf(q2,r2b.x, fmaf(q1,r1b.x, fmaf(q0,r0b.x, Ab.x*scale))));
            Ab.y = fmaf(q3,r3b.y, fmaf(q2,r2b.y, fmaf(q1,r1b.y, fmaf(q0,r0b.y, Ab.y*scale))));
            Ab.z = fmaf(q3,r3b.z, fmaf(q2,r2b.z, fmaf(q1,r1b.z, fmaf(q0,r0b.z, Ab.z*scale))));
            Ab.w = fmaf(q3,r3b.w, fmaf(q2,r2b.w, fmaf(q1,r1b.w, fmaf(q0,r0b.w, Ab.w*scale))));
            M = Mn;
        }
    }

    // combine 8 warps within the block
    __shared__ float sM[8], sL[8];
    __shared__ float sA[8][ND];
    float* arow = sA[w];
    arow[lane * 4 + 0] = Aa.x; arow[lane * 4 + 1] = Aa.y;
    arow[lane * 4 + 2] = Aa.z; arow[lane * 4 + 3] = Aa.w;
    arow[128 + lane * 4 + 0] = Ab.x; arow[128 + lane * 4 + 1] = Ab.y;
    arow[128 + lane * 4 + 2] = Ab.z; arow[128 + lane * 4 + 3] = Ab.w;
    if (lane == 0) { sM[w] = M; sL[w] = Lsum; }
    __syncthreads();

    float Mb = sM[0];
    #pragma unroll
    for (int j = 1; j < 8; j++) Mb = fmaxf(Mb, sM[j]);
    float acc = 0.f, lb = 0.f;
    #pragma unroll
    for (int j = 0; j < 8; j++) {
        float sc = __expf(sM[j] - Mb);   // sM=-1e30 (inactive warp) -> 0
        acc = fmaf(sc, sA[j][tid], acc);
        lb = fmaf(sc, sL[j], lb);
    }
    int pid = b * NCHUNK + chunk;
    g_PA[pid * ND + tid] = acc;
    if (tid == 0) { g_PM[pid] = Mb; g_PL[pid] = lb; }
}

// ---------------- K3: combine + context GEMV + alpha normalize -----------
__global__ void __launch_bounds__(256)
k_fin(const float* __restrict__ Wc_w, const float* __restrict__ Wc_b,
      const int* __restrict__ slen, float* __restrict__ alpha,
      float* __restrict__ out_ctx) {
    int b = blockIdx.x, t = threadIdx.x, w = t >> 5, lane = t & 31;
    int len = slen[b];
    int len_eff = (len == 0) ? NS : len;
    int nval = (len_eff + POS_PER_BLOCK - 1) / POS_PER_BLOCK;   // valid chunks

    __shared__ float sM[NCHUNK], sL[NCHUNK];
    __shared__ __align__(16) float sm[ND];
    if (t < NCHUNK) {
        sM[t] = (t < nval) ? g_PM[b * NCHUNK + t] : -1e30f;
        sL[t] = (t < nval) ? g_PL[b * NCHUNK + t] : 0.f;
    }
    __syncthreads();
    float Mg = sM[0];
    #pragma unroll 8
    for (int j = 1; j < NCHUNK; j++) Mg = fmaxf(Mg, sM[j]);
    float Lg = 0.f;
    #pragma unroll 8
    for (int j = 0; j < NCHUNK; j++) Lg = fmaf(sL[j], __expf(sM[j] - Mg), Lg);
    float m = 0.f;
    #pragma unroll 4
    for (int j = 0; j < nval; j++)
        m = fmaf(__expf(sM[j] - Mg), g_PA[(b * NCHUNK + j) * ND + t], m);
    float Rinv = 1.f / Lg;
    m *= Rinv;
    sm[t] = m;
    __syncthreads();

    // context GEMV: warp per output row
    const float4* m4 = (const float4*)sm;
    float4 ma = m4[lane], mb = m4[lane + 32];
    #pragma unroll
    for (int d = w; d < ND; d += 8) {
        const float4* wr = (const float4*)(Wc_w + d * ND);
        float4 wa = wr[lane], wb = wr[lane + 32];
        float p = wa.x*ma.x + wa.y*ma.y + wa.z*ma.z + wa.w*ma.w
                + wb.x*mb.x + wb.y*mb.y + wb.z*mb.z + wb.w*mb.w;
        #pragma unroll
        for (int o = 16; o > 0; o >>= 1)
            p += __shfl_xor_sync(0xffffffffu, p, o);
        if (lane == 0) out_ctx[b * ND + d] = p + Wc_b[d];
    }

    // normalize this batch's alpha: 2048 float4, 8 per thread, loads 8-deep
    float4* a4 = (float4*)(alpha + (size_t)b * NS);
    float4 ev[8];
    #pragma unroll
    for (int k = 0; k < 8; k++) ev[k] = a4[k * 256 + t];
    #pragma unroll
    for (int k = 0; k < 8; k++) {
        int pos = (k * 256 + t) * 4;
        float4 o;
        if (len > 0 && pos >= len) {           // fully masked group
            o = make_float4(0.f, 0.f, 0.f, 0.f);
        } else {
            o.x = (len > 0 && pos + 0 >= len) ? 0.f : __expf(ev[k].x - Mg) * Rinv;
            o.y = (len > 0 && pos + 1 >= len) ? 0.f : __expf(ev[k].y - Mg) * Rinv;
            o.z = (len > 0 && pos + 2 >= len) ? 0.f : __expf(ev[k].z - Mg) * Rinv;
            o.w = (len > 0 && pos + 3 >= len) ? 0.f : __expf(ev[k].w - Mg) * Rinv;
        }
        a4[k * 256 + t] = o;
    }
}

// ---------------- launch ----------------
extern "C" void kernel_launch(void* const* d_in, const int* in_sizes, int n_in,
                              void* d_out, int out_size) {
    const float* hs   = (const float*)d_in[0];  // [B,S,256]
    const float* ht   = (const float*)d_in[1];  // [B,256]
    const int*   slen = (const int*)  d_in[2];  // [B]
    const float* Wa_w = (const float*)d_in[3];  // [256,256]
    const float* Wa_b = (const float*)d_in[4];  // [256]
    const float* Wc_w = (const float*)d_in[5];  // [256,256]
    const float* Wc_b = (const float*)d_in[6];  // [256]

    float* alpha = (float*)d_out;                    // [B,S]
    float* ctx   = (float*)d_out + (size_t)NB * NS;  // [B,256]

    dim3 grid1(NPRE, NB);
    k_pre<<<grid1, 256>>>(ht, Wa_w, Wa_b);
    dim3 grid2(NCHUNK, NB);
    k_main<<<grid2, 256>>>(hs, slen, alpha);
    k_fin<<<NB, 256>>>(Wc_w, Wc_b, slen, alpha, ctx);
}